// round 1
// baseline (speedup 1.0000x reference)
#include <cuda_runtime.h>
#include <stdint.h>

#define TN 2000
#define UN 50000
#define TF 16
#define FP 40        // padded features: 0..35 = emb, 36 = count(1.0), 37..39 = 0
#define OUTC (TF + 36)
#define TB 128       // teams per block
#define NTB 16       // ceil(TN/TB) -> covers 2048 teams
#define TPAD (NTB * TB)
#define NS 50        // user splits
#define USPLIT (UN / NS)   // 1000
#define UT 32        // users per tile
#define RS 130       // smem mask row stride in floats (even, low-conflict)
#define NTHREADS 160 // 5 warps: warp w owns features [8w, 8w+8)

// ---------------- device scratch (static, no allocation) ----------------
__device__ float g_Upad[UN * FP];                       // 8 MB
__device__ float g_part[(size_t)NS * TPAD * FP];        // 16.4 MB partial sums

// ---------------- packed f32x2 FMA ----------------
__device__ __forceinline__ void fma2(unsigned long long& d,
                                     unsigned long long a,
                                     unsigned long long b) {
    asm("fma.rn.f32x2 %0, %1, %2, %0;" : "+l"(d) : "l"(a), "l"(b));
}
__device__ __forceinline__ float lo32(unsigned long long v) {
    return __uint_as_float((unsigned)(v & 0xffffffffu));
}
__device__ __forceinline__ float hi32(unsigned long long v) {
    return __uint_as_float((unsigned)(v >> 32));
}

// ---------------- prep: build padded U_emb [UN][FP] ----------------
__global__ void prep_kernel(const unsigned int* __restrict__ us_words,
                            const float* __restrict__ e0, const float* __restrict__ e1,
                            const float* __restrict__ e2, const float* __restrict__ e3,
                            const float* __restrict__ e4, const float* __restrict__ e5) {
    int u = blockIdx.x * blockDim.x + threadIdx.x;
    if (u >= UN) return;
    // detect int64 vs int32 serialization of U_static: int64 -> odd words are
    // all-zero high halves (indices are small non-negative).
    unsigned int probe = us_words[1] | us_words[3] | us_words[5] | us_words[7] |
                         us_words[9] | us_words[11] | us_words[13] | us_words[15];
    bool is64 = (probe == 0u);

    const float* tabs[6] = {e0, e1, e2, e3, e4, e5};
    float out[FP];
#pragma unroll
    for (int i = 0; i < 6; i++) {
        int elem = u * 6 + i;
        unsigned int idx = us_words[is64 ? (2 * elem) : elem];
        const float* row = tabs[i] + (size_t)idx * 6;
#pragma unroll
        for (int j = 0; j < 6; j++) out[i * 6 + j] = row[j];
    }
    out[36] = 1.0f;   // count column
    out[37] = 0.0f; out[38] = 0.0f; out[39] = 0.0f;

    float4* dst = (float4*)(g_Upad + (size_t)u * FP);
    const float4* src = (const float4*)out;
#pragma unroll
    for (int k = 0; k < FP / 4; k++) dst[k] = src[k];
}

// ---------------- main: masked GEMM accumulation ----------------
__global__ void __launch_bounds__(NTHREADS)
accum_kernel(const int* __restrict__ tum) {
    __shared__ float sM[UT * RS];                 // masks, transposed: [user][team]
    __shared__ unsigned long long sU[UT * FP];    // U tile, each float duplicated as f32x2

    const int bx = blockIdx.x;
    const int tb = bx & (NTB - 1);      // team block
    const int sp = bx >> 4;             // user split
    const int t0 = tb * TB;
    const int tid = threadIdx.x;
    const int w = tid >> 5;             // warp: feature group
    const int l = tid & 31;             // lane: team pairs {2l,2l+1} and {64+2l,65+2l}

    unsigned long long acc[2][8];
#pragma unroll
    for (int p = 0; p < 2; p++)
#pragma unroll
        for (int j = 0; j < 8; j++) acc[p][j] = 0ull;

    const int ub_begin = sp * USPLIT;
    const int ub_end = ub_begin + USPLIT;

    const float* mbase = sM + 2 * l;
    const unsigned long long* ubase = sU + 8 * w;

    for (int ub = ub_begin; ub < ub_end; ub += UT) {
        __syncthreads();  // protect previous tile's smem reads
        // ---- stage masks: 128 teams x 32 users, coalesced along users ----
        for (int idx = tid; idx < TB * UT; idx += NTHREADS) {
            int c = idx & (UT - 1);     // user within tile
            int r = idx >> 5;           // team within block
            int t = t0 + r;
            int u = ub + c;
            float m = 0.0f;
            if (t < TN && u < ub_end) {
                m = (tum[(size_t)t * UN + u] == 1) ? 1.0f : 0.0f;
            }
            sM[c * RS + r] = m;
        }
        // ---- stage U tile as duplicated f32x2: 32 users x 40 features ----
        for (int idx = tid; idx < UT * FP; idx += NTHREADS) {
            int c = idx / FP;
            int f = idx - c * FP;
            int u = ub + c;
            unsigned int bits = 0u;
            if (u < ub_end) bits = __float_as_uint(g_Upad[(size_t)u * FP + f]);
            sU[c * FP + f] = ((unsigned long long)bits << 32) | bits;
        }
        __syncthreads();

        // ---- compute: 16 f32x2 FMAs per thread per user ----
#pragma unroll 4
        for (int uu = 0; uu < UT; uu++) {
            const float* mr = mbase + uu * RS;
            unsigned long long m0 = *(const unsigned long long*)(mr);        // teams 2l,2l+1
            unsigned long long m1 = *(const unsigned long long*)(mr + 64);   // teams 64+2l,65+2l
            const unsigned long long* ur = ubase + uu * FP;
            ulonglong2 ua = *(const ulonglong2*)(ur + 0);
            ulonglong2 ub2 = *(const ulonglong2*)(ur + 2);
            ulonglong2 uc = *(const ulonglong2*)(ur + 4);
            ulonglong2 ud = *(const ulonglong2*)(ur + 6);
            fma2(acc[0][0], m0, ua.x);  fma2(acc[1][0], m1, ua.x);
            fma2(acc[0][1], m0, ua.y);  fma2(acc[1][1], m1, ua.y);
            fma2(acc[0][2], m0, ub2.x); fma2(acc[1][2], m1, ub2.x);
            fma2(acc[0][3], m0, ub2.y); fma2(acc[1][3], m1, ub2.y);
            fma2(acc[0][4], m0, uc.x);  fma2(acc[1][4], m1, uc.x);
            fma2(acc[0][5], m0, uc.y);  fma2(acc[1][5], m1, uc.y);
            fma2(acc[0][6], m0, ud.x);  fma2(acc[1][6], m1, ud.x);
            fma2(acc[0][7], m0, ud.y);  fma2(acc[1][7], m1, ud.y);
        }
    }

    // ---- epilogue: each (t,f) owned by exactly one thread per split ----
    float* part = g_part + (size_t)sp * (TPAD * FP);
    const int tA = t0 + 2 * l;
    const int tB2 = t0 + 64 + 2 * l;
#pragma unroll
    for (int j = 0; j < 8; j++) {
        int f = 8 * w + j;
        part[(size_t)tA * FP + f]        = lo32(acc[0][j]);
        part[(size_t)(tA + 1) * FP + f]  = hi32(acc[0][j]);
        part[(size_t)tB2 * FP + f]       = lo32(acc[1][j]);
        part[(size_t)(tB2 + 1) * FP + f] = hi32(acc[1][j]);
    }
}

// ---------------- finalize: reduce splits, divide by count, concat ----------------
__global__ void finalize_kernel(const float* __restrict__ T_static,
                                float* __restrict__ out) {
    int i = blockIdx.x * blockDim.x + threadIdx.x;
    if (i >= TN * OUTC) return;
    int t = i / OUTC;
    int c = i - t * OUTC;
    if (c < TF) {
        out[i] = T_static[t * TF + c];
    } else {
        int f = c - TF;
        float s = 0.0f, cnt = 0.0f;
        const float* p = g_part + (size_t)t * FP;
#pragma unroll 5
        for (int sp = 0; sp < NS; sp++) {
            const float* q = p + (size_t)sp * (TPAD * FP);
            s += q[f];
            cnt += q[36];
        }
        out[i] = s / cnt;
    }
}

extern "C" void kernel_launch(void* const* d_in, const int* in_sizes, int n_in,
                              void* d_out, int out_size) {
    const float* T_static = (const float*)d_in[0];
    const unsigned int* us_words = (const unsigned int*)d_in[1];
    const int* tum = (const int*)d_in[2];
    const float* e0 = (const float*)d_in[3];
    const float* e1 = (const float*)d_in[4];
    const float* e2 = (const float*)d_in[5];
    const float* e3 = (const float*)d_in[6];
    const float* e4 = (const float*)d_in[7];
    const float* e5 = (const float*)d_in[8];
    float* out = (float*)d_out;

    prep_kernel<<<(UN + 255) / 256, 256>>>(us_words, e0, e1, e2, e3, e4, e5);
    accum_kernel<<<NTB * NS, NTHREADS>>>(tum);
    finalize_kernel<<<(TN * OUTC + 255) / 256, 256>>>(T_static, out);
}

// round 3
// speedup vs baseline: 2.5055x; 2.5055x over previous
#include <cuda_runtime.h>
#include <cuda_bf16.h>
#include <stdint.h>

#define TN 2000
#define UN 50000
#define TF 16
#define OUTC (TF + 36)
#define NF 40                  // padded features: 0..35 emb, 36 count, 37..39 zero
#define KPAD 50176             // UN padded to multiple of 256
#define KT 256                 // K per tile
#define NTILES (KPAD / KT)     // 196
#define MB 128                 // M per CTA (4 warps x m32)
#define NMB 16                 // M blocks (covers 2048 teams)
#define TPAD (NMB * MB)        // 2048
#define NSPLIT 37              // K splits -> grid 592 = 4 CTAs/SM
#define NTHR 128
#define BSTRIDE 132            // B smem row stride in words (528 B, conflict-free)

// ---------------- device scratch (static) ----------------
__device__ __nv_bfloat16 g_UT[(size_t)NF * KPAD];        // U_emb^T bf16 [40][50176]
__device__ float g_part[(size_t)NSPLIT * TPAD * NF];     // per-split partials ~12 MB

// ---------------- mma.sync m16n8k16 bf16 ----------------
__device__ __forceinline__ void mma16816(float* c, uint32_t a0, uint32_t a1,
                                         uint32_t a2, uint32_t a3,
                                         uint32_t b0, uint32_t b1) {
    asm volatile("mma.sync.aligned.m16n8k16.row.col.f32.bf16.bf16.f32 "
                 "{%0,%1,%2,%3}, {%4,%5,%6,%7}, {%8,%9}, {%0,%1,%2,%3};"
                 : "+f"(c[0]), "+f"(c[1]), "+f"(c[2]), "+f"(c[3])
                 : "r"(a0), "r"(a1), "r"(a2), "r"(a3), "r"(b0), "r"(b1));
}
// load int2 mask pair -> packed bf16x2 {0,1}
__device__ __forceinline__ uint32_t lda(const int* p, int k, bool v) {
    uint32_t r = 0;
    if (v) {
        int2 m = __ldg((const int2*)(p + k));
        r = (m.x == 1 ? 0x3F80u : 0u) | (m.y == 1 ? 0x3F800000u : 0u);
    }
    return r;
}

// ---------------- prep: build U_emb^T bf16 [40][KPAD] ----------------
__global__ void prep_kernel(const unsigned int* __restrict__ us,
                            const float* __restrict__ e0, const float* __restrict__ e1,
                            const float* __restrict__ e2, const float* __restrict__ e3,
                            const float* __restrict__ e4, const float* __restrict__ e5) {
    __shared__ float sT[NF * 64];
    int u0 = blockIdx.x * 64;
    int tid = threadIdx.x;
    if (tid < 64) {
        int u = u0 + tid;
        if (u < UN) {
            // detect int64 vs int32 serialization of U_static
            unsigned probe = 0;
#pragma unroll
            for (int w = 1; w < 32; w += 2) probe |= us[w];
            bool is64 = (probe == 0u);
            const float* tabs[6] = {e0, e1, e2, e3, e4, e5};
#pragma unroll
            for (int i = 0; i < 6; i++) {
                int elem = u * 6 + i;
                unsigned idx = us[is64 ? (2 * elem) : elem];
                const float* row = tabs[i] + (size_t)idx * 6;
#pragma unroll
                for (int j = 0; j < 6; j++) sT[(i * 6 + j) * 64 + tid] = row[j];
            }
            sT[36 * 64 + tid] = 1.0f;  // count column
        } else {
#pragma unroll
            for (int f = 0; f < 37; f++) sT[f * 64 + tid] = 0.0f;
        }
        sT[37 * 64 + tid] = 0.0f;
        sT[38 * 64 + tid] = 0.0f;
        sT[39 * 64 + tid] = 0.0f;
    }
    __syncthreads();
    for (int idx = tid; idx < NF * 32; idx += blockDim.x) {
        int f = idx >> 5, p = idx & 31;
        __nv_bfloat162 v = __floats2bfloat162_rn(sT[f * 64 + 2 * p], sT[f * 64 + 2 * p + 1]);
        *(__nv_bfloat162*)(&g_UT[(size_t)f * KPAD + u0 + 2 * p]) = v;
    }
}

// ---------------- main: HMMA masked GEMM ----------------
__global__ void __launch_bounds__(NTHR) accum_kernel(const int* __restrict__ tum) {
    __shared__ uint32_t sB[NF * BSTRIDE];   // B tile [40 n][256 k] bf16, padded rows

    const int tid = threadIdx.x;
    const int w = tid >> 5, lane = tid & 31;
    const int g = lane >> 2, cc = lane & 3;
    const int mb = blockIdx.x & (NMB - 1);
    const int sp = blockIdx.x >> 4;
    const int t0 = mb * MB;

    // 4 row pointers per thread: rows t0 + w*32 + g + {0,8,16,24}
    const int* rp[4];
    bool rv[4];
#pragma unroll
    for (int i = 0; i < 4; i++) {
        int t = t0 + w * 32 + g + i * 8;
        rv[i] = (t < TN);
        rp[i] = tum + (size_t)(rv[i] ? t : 0) * UN;
    }

    float acc[2][5][4];
#pragma unroll
    for (int mh = 0; mh < 2; mh++)
#pragma unroll
        for (int nb = 0; nb < 5; nb++)
#pragma unroll
            for (int q = 0; q < 4; q++) acc[mh][nb][q] = 0.0f;

    for (int tile = sp; tile < NTILES; tile += NSPLIT) {
        const int k0 = tile * KT;
        __syncthreads();
        // stage B tile: 40 x 256 bf16, vectorized 8-bf16 chunks
#pragma unroll
        for (int j = 0; j < 10; j++) {
            int i = tid + j * NTHR;
            int n = i >> 5, km8 = i & 31;
            uint4 v = *(const uint4*)(&g_UT[(size_t)n * KPAD + k0 + km8 * 8]);
            *(uint4*)(&sB[n * BSTRIDE + km8 * 4]) = v;
        }
        __syncthreads();

#pragma unroll 4
        for (int ks = 0; ks < KT / 16; ks++) {
            const int kk = k0 + ks * 16 + 2 * cc;
            const bool kv0 = (kk < UN), kv1 = (kk + 8 < UN);
            // B fragments from smem (conflict-free)
            uint32_t bf[10];
            const int bw = ks * 8 + cc;
#pragma unroll
            for (int nb = 0; nb < 5; nb++) {
                int ro = (nb * 8 + g) * BSTRIDE + bw;
                bf[2 * nb] = sB[ro];
                bf[2 * nb + 1] = sB[ro + 4];
            }
#pragma unroll
            for (int mh = 0; mh < 2; mh++) {
                uint32_t a0 = lda(rp[2 * mh], kk, kv0 && rv[2 * mh]);
                uint32_t a1 = lda(rp[2 * mh + 1], kk, kv0 && rv[2 * mh + 1]);
                uint32_t a2 = lda(rp[2 * mh], kk + 8, kv1 && rv[2 * mh]);
                uint32_t a3 = lda(rp[2 * mh + 1], kk + 8, kv1 && rv[2 * mh + 1]);
#pragma unroll
                for (int nb = 0; nb < 5; nb++)
                    mma16816(acc[mh][nb], a0, a1, a2, a3, bf[2 * nb], bf[2 * nb + 1]);
            }
        }
    }

    // epilogue: write partials [sp][t][40]
    float* part = g_part + (size_t)sp * TPAD * NF;
#pragma unroll
    for (int mh = 0; mh < 2; mh++) {
        int tA = t0 + w * 32 + mh * 16 + g;
#pragma unroll
        for (int nb = 0; nb < 5; nb++) {
            int col = nb * 8 + 2 * cc;
            if (tA < TN)
                *(float2*)(&part[(size_t)tA * NF + col]) =
                    make_float2(acc[mh][nb][0], acc[mh][nb][1]);
            if (tA + 8 < TN)
                *(float2*)(&part[(size_t)(tA + 8) * NF + col]) =
                    make_float2(acc[mh][nb][2], acc[mh][nb][3]);
        }
    }
}

// ---------------- finalize: reduce splits, divide, concat ----------------
__global__ void finalize_kernel(const float* __restrict__ T_static,
                                float* __restrict__ out) {
    int i = blockIdx.x * blockDim.x + threadIdx.x;
    if (i >= TN * OUTC) return;
    int t = i / OUTC;
    int c = i - t * OUTC;
    if (c < TF) {
        out[i] = T_static[t * TF + c];
    } else {
        int f = c - TF;
        float s = 0.0f, cnt = 0.0f;
        const float* base = g_part + (size_t)t * NF;
        for (int k = 0; k < NSPLIT; k++) {
            const float* q = base + (size_t)k * (TPAD * NF);
            s += q[f];
            cnt += q[36];
        }
        out[i] = s / cnt;
    }
}

extern "C" void kernel_launch(void* const* d_in, const int* in_sizes, int n_in,
                              void* d_out, int out_size) {
    const float* T_static = (const float*)d_in[0];
    const unsigned int* us = (const unsigned int*)d_in[1];
    const int* tum = (const int*)d_in[2];
    const float* e0 = (const float*)d_in[3];
    const float* e1 = (const float*)d_in[4];
    const float* e2 = (const float*)d_in[5];
    const float* e3 = (const float*)d_in[6];
    const float* e4 = (const float*)d_in[7];
    const float* e5 = (const float*)d_in[8];
    float* out = (float*)d_out;

    prep_kernel<<<KPAD / 64, 256>>>(us, e0, e1, e2, e3, e4, e5);
    accum_kernel<<<NMB * NSPLIT, NTHR>>>(tum);
    finalize_kernel<<<(TN * OUTC + 255) / 256, 256>>>(T_static, out);
}

// round 4
// speedup vs baseline: 4.2733x; 1.7056x over previous
#include <cuda_runtime.h>
#include <cuda_bf16.h>
#include <stdint.h>

#define TN 2000
#define UN 50000
#define TF 16
#define OUTC (TF + 36)
#define NF 40                  // padded features: 0..35 emb, 36 count, 37..39 zero
#define KPAD 50176             // UN padded to multiple of 256
#define KT 256                 // K per tile
#define NTILES (KPAD / KT)     // 196
#define MB 128                 // M per CTA (4 warps x m32)
#define NMB 16                 // M blocks (covers 2048 teams)
#define TPAD (NMB * MB)        // 2048
#define NSPLIT 37              // K splits -> grid 592 = 4 CTAs/SM, one full wave
#define NTHR 128
#define BSTR 136               // B smem row stride in words (conflict-free for LDS.64)

// ---------------- device scratch (static) ----------------
__device__ __nv_bfloat16 g_UT[(size_t)NF * KPAD];        // U_emb^T bf16 [40][50176]
__device__ float g_part[(size_t)NSPLIT * TPAD * NF];     // per-split partials ~12 MB

// ---------------- mma.sync m16n8k16 bf16 ----------------
__device__ __forceinline__ void mma16816(float* c, uint32_t a0, uint32_t a1,
                                         uint32_t a2, uint32_t a3,
                                         uint32_t b0, uint32_t b1) {
    asm volatile("mma.sync.aligned.m16n8k16.row.col.f32.bf16.bf16.f32 "
                 "{%0,%1,%2,%3}, {%4,%5,%6,%7}, {%8,%9}, {%0,%1,%2,%3};"
                 : "+f"(c[0]), "+f"(c[1]), "+f"(c[2]), "+f"(c[3])
                 : "r"(a0), "r"(a1), "r"(a2), "r"(a3), "r"(b0), "r"(b1));
}
// mask pair {0,1} -> packed bf16x2 {0.0,1.0}: 2 IMADs
__device__ __forceinline__ uint32_t pk(int2 m) {
    return (uint32_t)(m.x + (m.y << 16)) * 0x3F80u;
}

// ---------------- prep: build U_emb^T bf16 [40][KPAD] ----------------
__global__ void prep_kernel(const unsigned int* __restrict__ us,
                            const float* __restrict__ e0, const float* __restrict__ e1,
                            const float* __restrict__ e2, const float* __restrict__ e3,
                            const float* __restrict__ e4, const float* __restrict__ e5) {
    __shared__ float sT[NF * 64];
    int u0 = blockIdx.x * 64;
    int tid = threadIdx.x;
    if (tid < 64) {
        int u = u0 + tid;
        if (u < UN) {
            unsigned probe = 0;
#pragma unroll
            for (int w = 1; w < 32; w += 2) probe |= us[w];
            bool is64 = (probe == 0u);   // int64 serialization -> zero high words
            const float* tabs[6] = {e0, e1, e2, e3, e4, e5};
#pragma unroll
            for (int i = 0; i < 6; i++) {
                int elem = u * 6 + i;
                unsigned idx = us[is64 ? (2 * elem) : elem];
                const float* row = tabs[i] + (size_t)idx * 6;
#pragma unroll
                for (int j = 0; j < 6; j++) sT[(i * 6 + j) * 64 + tid] = row[j];
            }
            sT[36 * 64 + tid] = 1.0f;  // count column
        } else {
#pragma unroll
            for (int f = 0; f < 37; f++) sT[f * 64 + tid] = 0.0f;
        }
        sT[37 * 64 + tid] = 0.0f;
        sT[38 * 64 + tid] = 0.0f;
        sT[39 * 64 + tid] = 0.0f;
    }
    __syncthreads();
    for (int idx = tid; idx < NF * 32; idx += blockDim.x) {
        int f = idx >> 5, p = idx & 31;
        __nv_bfloat162 v = __floats2bfloat162_rn(sT[f * 64 + 2 * p], sT[f * 64 + 2 * p + 1]);
        *(__nv_bfloat162*)(&g_UT[(size_t)f * KPAD + u0 + 2 * p]) = v;
    }
}

// ---------------- main: HMMA masked GEMM with deep A prefetch ----------------
struct ARegs { int2 v[8]; };

template <bool G>
__device__ __forceinline__ void loadA(ARegs& d, const int* const* rp, int kk) {
#pragma unroll
    for (int r = 0; r < 4; r++) {
        if (!G) {
            d.v[2 * r]     = *(const int2*)(rp[r] + kk);
            d.v[2 * r + 1] = *(const int2*)(rp[r] + kk + 8);
        } else {
            d.v[2 * r]     = (kk < UN)     ? *(const int2*)(rp[r] + kk)     : make_int2(0, 0);
            d.v[2 * r + 1] = (kk + 8 < UN) ? *(const int2*)(rp[r] + kk + 8) : make_int2(0, 0);
        }
    }
}

template <bool G>
__device__ __forceinline__ void tile_body(const int* const* rp, const uint32_t* sB,
                                          float acc[2][5][4], int k0, int g, int cc) {
    ARegs ab[2];
    const int kbase = k0 + 2 * cc;
    loadA<G>(ab[0], rp, kbase);
    loadA<G>(ab[1], rp, kbase + 16);
#pragma unroll
    for (int ks = 0; ks < KT / 16; ks++) {
        const int b = ks & 1;
        // pack current A fragments (frees ab[b] for the prefetch below)
        uint32_t a[8];
#pragma unroll
        for (int j = 0; j < 8; j++) a[j] = pk(ab[b].v[j]);
        // prefetch distance 2
        if (ks + 2 < KT / 16) loadA<G>(ab[b], rp, kbase + (ks + 2) * 16);
        // B fragments: one LDS.64 per n-block, conflict-free
        uint32_t bf[10];
        const int bw = ks * 8 + cc * 2;
#pragma unroll
        for (int nb = 0; nb < 5; nb++) {
            uint2 v = *(const uint2*)&sB[(nb * 8 + g) * BSTR + bw];
            bf[2 * nb] = v.x;
            bf[2 * nb + 1] = v.y;
        }
#pragma unroll
        for (int nb = 0; nb < 5; nb++) {
            mma16816(acc[0][nb], a[0], a[2], a[1], a[3], bf[2 * nb], bf[2 * nb + 1]);
            mma16816(acc[1][nb], a[4], a[6], a[5], a[7], bf[2 * nb], bf[2 * nb + 1]);
        }
    }
}

__global__ void __launch_bounds__(NTHR) accum_kernel(const int* __restrict__ tum) {
    __shared__ uint32_t sB[NF * BSTR];   // B tile: paired (b0,b1) layout

    const int tid = threadIdx.x;
    const int w = tid >> 5, lane = tid & 31;
    const int g = lane >> 2, cc = lane & 3;
    const int mb = blockIdx.x & (NMB - 1);
    const int sp = blockIdx.x >> 4;
    const int t0 = mb * MB;

    // row pointers; invalid rows alias row 0 (results discarded in epilogue)
    const int* rp[4];
#pragma unroll
    for (int i = 0; i < 4; i++) {
        int t = t0 + w * 32 + g + i * 8;
        rp[i] = tum + (size_t)(t < TN ? t : 0) * UN;
    }

    float acc[2][5][4];
#pragma unroll
    for (int mh = 0; mh < 2; mh++)
#pragma unroll
        for (int nb = 0; nb < 5; nb++)
#pragma unroll
            for (int q = 0; q < 4; q++) acc[mh][nb][q] = 0.0f;

    for (int tile = sp; tile < NTILES; tile += NSPLIT) {
        const int k0 = tile * KT;
        __syncthreads();
        // stage B: for each (n, ks, cc) store pair {k=16ks+2cc, k=16ks+2cc+8} adjacent
        for (int i = tid; i < NF * 64; i += NTHR) {
            int n = i >> 6;
            int r = i & 63;              // r = ks*4 + cc
            const uint32_t* src = (const uint32_t*)(g_UT + (size_t)n * KPAD + k0);
            int ks = r >> 2, c2 = r & 3;
            uint32_t w0 = src[ks * 8 + c2];
            uint32_t w1 = src[ks * 8 + c2 + 4];
            *(uint2*)&sB[n * BSTR + ks * 8 + c2 * 2] = make_uint2(w0, w1);
        }
        __syncthreads();

        if (tile == NTILES - 1)
            tile_body<true>(rp, sB, acc, k0, g, cc);
        else
            tile_body<false>(rp, sB, acc, k0, g, cc);
    }

    // epilogue: write partials [sp][t][40]
    float* part = g_part + (size_t)sp * TPAD * NF;
#pragma unroll
    for (int mh = 0; mh < 2; mh++) {
        int tA = t0 + w * 32 + mh * 16 + g;
#pragma unroll
        for (int nb = 0; nb < 5; nb++) {
            int col = nb * 8 + 2 * cc;
            if (tA < TN)
                *(float2*)(&part[(size_t)tA * NF + col]) =
                    make_float2(acc[mh][nb][0], acc[mh][nb][1]);
            if (tA + 8 < TN)
                *(float2*)(&part[(size_t)(tA + 8) * NF + col]) =
                    make_float2(acc[mh][nb][2], acc[mh][nb][3]);
        }
    }
}

// ---------------- finalize: reduce splits, divide, concat ----------------
__global__ void finalize_kernel(const float* __restrict__ T_static,
                                float* __restrict__ out) {
    int i = blockIdx.x * blockDim.x + threadIdx.x;
    if (i >= TN * OUTC) return;
    int t = i / OUTC;
    int c = i - t * OUTC;
    if (c < TF) {
        out[i] = T_static[t * TF + c];
    } else {
        int f = c - TF;
        float s = 0.0f, cnt = 0.0f;
        const float* base = g_part + (size_t)t * NF;
        for (int k = 0; k < NSPLIT; k++) {
            const float* q = base + (size_t)k * (TPAD * NF);
            s += q[f];
            cnt += q[36];
        }
        out[i] = s / cnt;
    }
}

extern "C" void kernel_launch(void* const* d_in, const int* in_sizes, int n_in,
                              void* d_out, int out_size) {
    const float* T_static = (const float*)d_in[0];
    const unsigned int* us = (const unsigned int*)d_in[1];
    const int* tum = (const int*)d_in[2];
    const float* e0 = (const float*)d_in[3];
    const float* e1 = (const float*)d_in[4];
    const float* e2 = (const float*)d_in[5];
    const float* e3 = (const float*)d_in[6];
    const float* e4 = (const float*)d_in[7];
    const float* e5 = (const float*)d_in[8];
    float* out = (float*)d_out;

    prep_kernel<<<KPAD / 64, 256>>>(us, e0, e1, e2, e3, e4, e5);
    accum_kernel<<<NMB * NSPLIT, NTHR>>>(tum);
    finalize_kernel<<<(TN * OUTC + 255) / 256, 256>>>(T_static, out);
}

// round 5
// speedup vs baseline: 5.3744x; 1.2577x over previous
#include <cuda_runtime.h>
#include <cuda_bf16.h>
#include <stdint.h>

#define TN 2000
#define UN 50000
#define TF 16
#define OUTC (TF + 36)
#define NF 40                   // padded features: 0..35 emb, 36 count, 37..39 zero
#define KPAD 50176              // mult of 64
#define KT2 64                  // K per pipeline stage
#define NST_TOT (KPAD / KT2)    // 784
#define MB 128                  // M per CTA (8 warps x m16)
#define NMB 16
#define TPAD (NMB * MB)         // 2048
#define NSPLIT 9                // grid = 144 CTAs ~ 1/SM
#define NTHR 256
#define NSTG 5
#define ASTR 68                              // A row stride (ints)
#define ASTAGE_B (128 * ASTR * 4)            // 34816 B
#define BSTR 36                              // B row stride (words)
#define BSTAGE_B (NF * BSTR * 4)             // 5760 B
#define SMEM_TOTAL (NSTG * (ASTAGE_B + BSTAGE_B))   // 202880 B

// ---------------- device scratch (static, zero-init) ----------------
__device__ __nv_bfloat16 g_UT[(size_t)NF * KPAD];
__device__ float g_part[(size_t)NSPLIT * TPAD * NF];

__device__ __forceinline__ uint32_t smem_u32(const void* p) {
    uint32_t a;
    asm("{ .reg .u64 t; cvta.to.shared.u64 t, %1; cvt.u32.u64 %0, t; }" : "=r"(a) : "l"(p));
    return a;
}
__device__ __forceinline__ void mma16816(float* c, uint32_t a0, uint32_t a1,
                                         uint32_t a2, uint32_t a3,
                                         uint32_t b0, uint32_t b1) {
    asm volatile("mma.sync.aligned.m16n8k16.row.col.f32.bf16.bf16.f32 "
                 "{%0,%1,%2,%3}, {%4,%5,%6,%7}, {%8,%9}, {%0,%1,%2,%3};"
                 : "+f"(c[0]), "+f"(c[1]), "+f"(c[2]), "+f"(c[3])
                 : "r"(a0), "r"(a1), "r"(a2), "r"(a3), "r"(b0), "r"(b1));
}
// mask pair {0,1} -> packed bf16x2 {0.0,1.0}
__device__ __forceinline__ uint32_t pk(int2 m) {
    return (uint32_t)(m.x + (m.y << 16)) * 0x3F80u;
}

// ---------------- prep: build U_emb^T bf16 [40][KPAD] ----------------
__global__ void prep_kernel(const unsigned int* __restrict__ us,
                            const float* __restrict__ e0, const float* __restrict__ e1,
                            const float* __restrict__ e2, const float* __restrict__ e3,
                            const float* __restrict__ e4, const float* __restrict__ e5) {
    __shared__ float sT[NF * 64];
    int u0 = blockIdx.x * 64;
    int tid = threadIdx.x;
    if (tid < 64) {
        int u = u0 + tid;
        if (u < UN) {
            unsigned probe = 0;
#pragma unroll
            for (int w = 1; w < 32; w += 2) probe |= us[w];
            bool is64 = (probe == 0u);
            const float* tabs[6] = {e0, e1, e2, e3, e4, e5};
#pragma unroll
            for (int i = 0; i < 6; i++) {
                int elem = u * 6 + i;
                unsigned idx = us[is64 ? (2 * elem) : elem];
                const float* row = tabs[i] + (size_t)idx * 6;
#pragma unroll
                for (int j = 0; j < 6; j++) sT[(i * 6 + j) * 64 + tid] = row[j];
            }
            sT[36 * 64 + tid] = 1.0f;
        } else {
#pragma unroll
            for (int f = 0; f < 37; f++) sT[f * 64 + tid] = 0.0f;
        }
        sT[37 * 64 + tid] = 0.0f;
        sT[38 * 64 + tid] = 0.0f;
        sT[39 * 64 + tid] = 0.0f;
    }
    __syncthreads();
    for (int idx = tid; idx < NF * 32; idx += blockDim.x) {
        int f = idx >> 5, p = idx & 31;
        __nv_bfloat162 v = __floats2bfloat162_rn(sT[f * 64 + 2 * p], sT[f * 64 + 2 * p + 1]);
        *(__nv_bfloat162*)(&g_UT[(size_t)f * KPAD + u0 + 2 * p]) = v;
    }
}

// ---------------- accum: cp.async multistage HMMA GEMM ----------------
__device__ __forceinline__ void issue_stage(uint32_t smb, int s, int k0,
                                            const int* __restrict__ tum,
                                            int t0, int tid) {
    uint32_t aB = smb + s * ASTAGE_B;
    uint32_t bB = smb + NSTG * ASTAGE_B + s * BSTAGE_B;
    // A: 128 rows x 64 ints, 2048 16B-chunks
#pragma unroll
    for (int i = 0; i < 8; i++) {
        int q = tid + i * NTHR;
        int r = q >> 4;
        int c = (q & 15) << 2;
        uint32_t dst = aB + (uint32_t)(r * ASTR + c) * 4u;
        const int* src = tum + (size_t)(t0 + r) * UN + (k0 + c);
        uint32_t sz = ((t0 + r) < TN && (k0 + c) < UN) ? 16u : 0u;
        asm volatile("cp.async.cg.shared.global [%0], [%1], 16, %2;"
                     :: "r"(dst), "l"(src), "r"(sz));
    }
    // B: 40 rows x 64 bf16, 320 16B-chunks (g_UT zero-padded to KPAD)
#pragma unroll
    for (int i = 0; i < 2; i++) {
        int q = tid + i * NTHR;
        if (q < NF * 8) {
            int r = q >> 3;
            uint32_t dst = bB + (uint32_t)(r * BSTR) * 4u + (uint32_t)(q & 7) * 16u;
            const __nv_bfloat16* src = g_UT + (size_t)r * KPAD + k0 + (q & 7) * 8;
            asm volatile("cp.async.cg.shared.global [%0], [%1], 16, 16;"
                         :: "r"(dst), "l"(src));
        }
    }
}

__device__ __forceinline__ void compute_stage(const char* sm, int s, float acc[5][4],
                                              int w, int g, int cc) {
    const int* aP = (const int*)(sm + s * ASTAGE_B);
    const uint32_t* bP = (const uint32_t*)(sm + NSTG * ASTAGE_B + s * BSTAGE_B);
    const int rowA = (16 * w + g) * ASTR + 2 * cc;
#pragma unroll
    for (int ks2 = 0; ks2 < 4; ks2++) {
        const int* b0p = aP + rowA + 16 * ks2;
        int2 x0 = *(const int2*)(b0p);
        int2 x2 = *(const int2*)(b0p + 8);
        int2 x1 = *(const int2*)(b0p + 8 * ASTR);
        int2 x3 = *(const int2*)(b0p + 8 * ASTR + 8);
        uint32_t a0 = pk(x0), a1 = pk(x1), a2 = pk(x2), a3 = pk(x3);
        const uint32_t* bb = bP + g * BSTR + 8 * ks2 + cc;
#pragma unroll
        for (int nb = 0; nb < 5; nb++) {
            uint32_t b0 = bb[nb * 8 * BSTR];
            uint32_t b1 = bb[nb * 8 * BSTR + 4];
            mma16816(acc[nb], a0, a1, a2, a3, b0, b1);
        }
    }
}

__global__ void __launch_bounds__(NTHR) accum_kernel(const int* __restrict__ tum) {
    extern __shared__ char sm[];
    const int tid = threadIdx.x;
    const int w = tid >> 5, lane = tid & 31;
    const int g = lane >> 2, cc = lane & 3;
    const int mb = blockIdx.x & (NMB - 1);
    const int sp = blockIdx.x >> 4;
    const int t0 = mb * MB;
    const uint32_t smb = smem_u32(sm);

    const int J = (NST_TOT - sp + NSPLIT - 1) / NSPLIT;   // stages for this split

    float acc[5][4];
#pragma unroll
    for (int nb = 0; nb < 5; nb++)
#pragma unroll
        for (int q = 0; q < 4; q++) acc[nb][q] = 0.0f;

    // prologue: NSTG-1 stages in flight
#pragma unroll
    for (int s = 0; s < NSTG - 1; s++) {
        if (s < J) issue_stage(smb, s, (sp + s * NSPLIT) * KT2, tum, t0, tid);
        asm volatile("cp.async.commit_group;");
    }
    for (int j = 0; j < J; j++) {
        asm volatile("cp.async.wait_group %0;" :: "n"(NSTG - 2));
        __syncthreads();
        int nj = j + NSTG - 1;
        if (nj < J)
            issue_stage(smb, nj % NSTG, (sp + nj * NSPLIT) * KT2, tum, t0, tid);
        asm volatile("cp.async.commit_group;");
        compute_stage(sm, j % NSTG, acc, w, g, cc);
    }

    // epilogue
    float* part = g_part + (size_t)sp * TPAD * NF;
    int tA = t0 + 16 * w + g;
#pragma unroll
    for (int nb = 0; nb < 5; nb++) {
        int col = nb * 8 + 2 * cc;
        if (tA < TN)
            *(float2*)(&part[(size_t)tA * NF + col]) = make_float2(acc[nb][0], acc[nb][1]);
        if (tA + 8 < TN)
            *(float2*)(&part[(size_t)(tA + 8) * NF + col]) = make_float2(acc[nb][2], acc[nb][3]);
    }
}

// ---------------- finalize ----------------
__global__ void finalize_kernel(const float* __restrict__ T_static,
                                float* __restrict__ out) {
    int i = blockIdx.x * blockDim.x + threadIdx.x;
    if (i >= TN * OUTC) return;
    int t = i / OUTC;
    int c = i - t * OUTC;
    if (c < TF) {
        out[i] = T_static[t * TF + c];
    } else {
        int f = c - TF;
        float s = 0.0f, cnt = 0.0f;
        const float* base = g_part + (size_t)t * NF;
#pragma unroll
        for (int k = 0; k < NSPLIT; k++) {
            const float* q = base + (size_t)k * (TPAD * NF);
            s += q[f];
            cnt += q[36];
        }
        out[i] = s / cnt;
    }
}

extern "C" void kernel_launch(void* const* d_in, const int* in_sizes, int n_in,
                              void* d_out, int out_size) {
    const float* T_static = (const float*)d_in[0];
    const unsigned int* us = (const unsigned int*)d_in[1];
    const int* tum = (const int*)d_in[2];
    const float* e0 = (const float*)d_in[3];
    const float* e1 = (const float*)d_in[4];
    const float* e2 = (const float*)d_in[5];
    const float* e3 = (const float*)d_in[6];
    const float* e4 = (const float*)d_in[7];
    const float* e5 = (const float*)d_in[8];
    float* out = (float*)d_out;

    cudaFuncSetAttribute(accum_kernel, cudaFuncAttributeMaxDynamicSharedMemorySize,
                         SMEM_TOTAL);
    prep_kernel<<<KPAD / 64, 256>>>(us, e0, e1, e2, e3, e4, e5);
    accum_kernel<<<NMB * NSPLIT, NTHR, SMEM_TOTAL>>>(tum);
    finalize_kernel<<<(TN * OUTC + 255) / 256, 256>>>(T_static, out);
}

// round 6
// speedup vs baseline: 6.3924x; 1.1894x over previous
#include <cuda_runtime.h>
#include <cuda_bf16.h>
#include <stdint.h>

#define TN 2000
#define UN 50000
#define TF 16
#define OUTC (TF + 36)
#define NF 40                   // padded features: 0..35 emb, 36 count, 37..39 zero
#define KPAD 50176              // mult of 64
#define KT2 64                  // K per pipeline stage
#define NST_TOT (KPAD / KT2)    // 784
#define MB 128                  // M per CTA (4 warps x m32)
#define NMB 16
#define TPAD (NMB * MB)         // 2048
#define NSPLIT 18               // grid = 288 CTAs ~ 2/SM
#define NTHR 128
#define ASTR 72                              // A row stride (ints): conflict-free, 288B
#define ASTAGE_B (128 * ASTR * 4)            // 36864 B
#define BSTR 40                              // B row stride (words): conflict-free, 160B
#define BSTAGE_B (NF * BSTR * 4)             // 6400 B
#define SMEM_TOTAL (2 * (ASTAGE_B + BSTAGE_B))   // 86528 B

// ---------------- device scratch (static, zero-init) ----------------
__device__ __nv_bfloat16 g_UT[(size_t)NF * KPAD];   // paired-word layout per 64k block
__device__ float g_part[(size_t)NSPLIT * TPAD * NF];

__device__ __forceinline__ uint32_t smem_u32(const void* p) {
    uint32_t a;
    asm("{ .reg .u64 t; cvta.to.shared.u64 t, %1; cvt.u32.u64 %0, t; }" : "=r"(a) : "l"(p));
    return a;
}
__device__ __forceinline__ void mma16816(float* c, uint32_t a0, uint32_t a1,
                                         uint32_t a2, uint32_t a3,
                                         uint32_t b0, uint32_t b1) {
    asm volatile("mma.sync.aligned.m16n8k16.row.col.f32.bf16.bf16.f32 "
                 "{%0,%1,%2,%3}, {%4,%5,%6,%7}, {%8,%9}, {%0,%1,%2,%3};"
                 : "+f"(c[0]), "+f"(c[1]), "+f"(c[2]), "+f"(c[3])
                 : "r"(a0), "r"(a1), "r"(a2), "r"(a3), "r"(b0), "r"(b1));
}
__device__ __forceinline__ uint32_t pk(int2 m) {
    return (uint32_t)(m.x + (m.y << 16)) * 0x3F80u;
}

// ---------------- prep: build U_emb^T bf16, paired-word layout ----------------
// Within each 64-k block: orig word p (elements 2p,2p+1) stored at word
// w' = (p>>3)*8 + (p&3)*2 + ((p>>2)&1), so LDS.64 at ks*8+cc*2 yields the
// (b0,b1) fragment pair directly.
__global__ void prep_kernel(const unsigned int* __restrict__ us,
                            const float* __restrict__ e0, const float* __restrict__ e1,
                            const float* __restrict__ e2, const float* __restrict__ e3,
                            const float* __restrict__ e4, const float* __restrict__ e5) {
    __shared__ float sT[NF * 64];
    int u0 = blockIdx.x * 64;
    int tid = threadIdx.x;
    if (tid < 64) {
        int u = u0 + tid;
        if (u < UN) {
            unsigned probe = 0;
#pragma unroll
            for (int w = 1; w < 32; w += 2) probe |= us[w];
            bool is64 = (probe == 0u);
            const float* tabs[6] = {e0, e1, e2, e3, e4, e5};
#pragma unroll
            for (int i = 0; i < 6; i++) {
                int elem = u * 6 + i;
                unsigned idx = us[is64 ? (2 * elem) : elem];
                const float* row = tabs[i] + (size_t)idx * 6;
#pragma unroll
                for (int j = 0; j < 6; j++) sT[(i * 6 + j) * 64 + tid] = row[j];
            }
            sT[36 * 64 + tid] = 1.0f;
        } else {
#pragma unroll
            for (int f = 0; f < 37; f++) sT[f * 64 + tid] = 0.0f;
        }
        sT[37 * 64 + tid] = 0.0f;
        sT[38 * 64 + tid] = 0.0f;
        sT[39 * 64 + tid] = 0.0f;
    }
    __syncthreads();
    for (int idx = tid; idx < NF * 32; idx += blockDim.x) {
        int f = idx >> 5, p = idx & 31;
        int wp = ((p >> 3) << 3) + ((p & 3) << 1) + ((p >> 2) & 1);
        __nv_bfloat162 v = __floats2bfloat162_rn(sT[f * 64 + 2 * p], sT[f * 64 + 2 * p + 1]);
        *(__nv_bfloat162*)(&g_UT[(size_t)f * KPAD + u0 + 2 * wp]) = v;
    }
}

// ---------------- accum: cp.async depth-2 HMMA GEMM, m32/warp ----------------
__device__ __forceinline__ void issue_stage(uint32_t smb, int s, int k0,
                                            const int* __restrict__ tum,
                                            int t0, int tid) {
    uint32_t aB = smb + s * ASTAGE_B;
    uint32_t bB = smb + 2 * ASTAGE_B + s * BSTAGE_B;
    // A: 128 rows x 64 ints = 2048 16B chunks
#pragma unroll
    for (int i = 0; i < 16; i++) {
        int q = tid + i * NTHR;
        int r = q >> 4;
        int c = (q & 15) << 2;
        uint32_t dst = aB + (uint32_t)r * (ASTR * 4) + (uint32_t)(q & 15) * 16u;
        const int* src = tum + (size_t)(t0 + r) * UN + (k0 + c);
        uint32_t sz = ((t0 + r) < TN && (k0 + c) < UN) ? 16u : 0u;
        asm volatile("cp.async.cg.shared.global [%0], [%1], 16, %2;"
                     :: "r"(dst), "l"(src), "r"(sz));
    }
    // B: 40 rows x 32 words = 320 16B chunks
#pragma unroll
    for (int i = 0; i < 3; i++) {
        int q = tid + i * NTHR;
        if (q < NF * 8) {
            int r = q >> 3;
            uint32_t dst = bB + (uint32_t)r * (BSTR * 4) + (uint32_t)(q & 7) * 16u;
            const __nv_bfloat16* src = g_UT + (size_t)r * KPAD + k0 + (q & 7) * 8;
            asm volatile("cp.async.cg.shared.global [%0], [%1], 16, 16;"
                         :: "r"(dst), "l"(src));
        }
    }
}

__device__ __forceinline__ void compute_stage(const char* sm, int s, float acc[2][5][4],
                                              int w, int g, int cc) {
    const int* aP = (const int*)(sm + s * ASTAGE_B);
    const uint32_t* bP = (const uint32_t*)(sm + 2 * ASTAGE_B + s * BSTAGE_B);
    const int rowA = (32 * w + g) * ASTR + 2 * cc;
#pragma unroll
    for (int ks = 0; ks < 4; ks++) {
        // B fragments: 5 LDS.64, conflict-free, shared by both M-halves
        uint32_t bf[10];
        const uint32_t* bb = bP + g * BSTR + ks * 8 + cc * 2;
#pragma unroll
        for (int nb = 0; nb < 5; nb++) {
            uint2 v = *(const uint2*)(bb + nb * 8 * BSTR);
            bf[2 * nb] = v.x;
            bf[2 * nb + 1] = v.y;
        }
#pragma unroll
        for (int mh = 0; mh < 2; mh++) {
            const int* p0 = aP + rowA + mh * 16 * ASTR + 16 * ks;
            int2 x0 = *(const int2*)(p0);
            int2 x2 = *(const int2*)(p0 + 8);
            int2 x1 = *(const int2*)(p0 + 8 * ASTR);
            int2 x3 = *(const int2*)(p0 + 8 * ASTR + 8);
            uint32_t a0 = pk(x0), a1 = pk(x1), a2 = pk(x2), a3 = pk(x3);
#pragma unroll
            for (int nb = 0; nb < 5; nb++)
                mma16816(acc[mh][nb], a0, a1, a2, a3, bf[2 * nb], bf[2 * nb + 1]);
        }
    }
}

__global__ void __launch_bounds__(NTHR, 2) accum_kernel(const int* __restrict__ tum) {
    extern __shared__ char sm[];
    const int tid = threadIdx.x;
    const int w = tid >> 5, lane = tid & 31;
    const int g = lane >> 2, cc = lane & 3;
    const int mb = blockIdx.x & (NMB - 1);
    const int sp = blockIdx.x >> 4;
    const int t0 = mb * MB;
    const uint32_t smb = smem_u32(sm);

    const int J = (NST_TOT - sp + NSPLIT - 1) / NSPLIT;

    float acc[2][5][4];
#pragma unroll
    for (int mh = 0; mh < 2; mh++)
#pragma unroll
        for (int nb = 0; nb < 5; nb++)
#pragma unroll
            for (int q = 0; q < 4; q++) acc[mh][nb][q] = 0.0f;

    // prologue: stage 0 in flight
    issue_stage(smb, 0, sp * KT2, tum, t0, tid);
    asm volatile("cp.async.commit_group;");

    for (int j = 0; j < J; j++) {
        __syncthreads();   // buffer (j+1)&1 free: compute(j-1) done by all warps
        if (j + 1 < J) {
            issue_stage(smb, (j + 1) & 1, (sp + (j + 1) * NSPLIT) * KT2, tum, t0, tid);
            asm volatile("cp.async.commit_group;");
            asm volatile("cp.async.wait_group 1;");   // in-order: group j retired
        } else {
            asm volatile("cp.async.wait_group 0;");
        }
        __syncthreads();
        compute_stage(sm, j & 1, acc, w, g, cc);
    }

    // epilogue: write partials [sp][t][40]
    float* part = g_part + (size_t)sp * TPAD * NF;
#pragma unroll
    for (int mh = 0; mh < 2; mh++) {
        int tA = t0 + 32 * w + 16 * mh + g;
#pragma unroll
        for (int nb = 0; nb < 5; nb++) {
            int col = nb * 8 + 2 * cc;
            if (tA < TN)
                *(float2*)(&part[(size_t)tA * NF + col]) =
                    make_float2(acc[mh][nb][0], acc[mh][nb][1]);
            if (tA + 8 < TN)
                *(float2*)(&part[(size_t)(tA + 8) * NF + col]) =
                    make_float2(acc[mh][nb][2], acc[mh][nb][3]);
        }
    }
}

// ---------------- finalize ----------------
__global__ void finalize_kernel(const float* __restrict__ T_static,
                                float* __restrict__ out) {
    int i = blockIdx.x * blockDim.x + threadIdx.x;
    if (i >= TN * OUTC) return;
    int t = i / OUTC;
    int c = i - t * OUTC;
    if (c < TF) {
        out[i] = T_static[t * TF + c];
    } else {
        int f = c - TF;
        float s = 0.0f, cnt = 0.0f;
        const float* base = g_part + (size_t)t * NF;
#pragma unroll
        for (int k = 0; k < NSPLIT; k++) {
            const float* q = base + (size_t)k * (TPAD * NF);
            s += q[f];
            cnt += q[36];
        }
        out[i] = s / cnt;
    }
}

extern "C" void kernel_launch(void* const* d_in, const int* in_sizes, int n_in,
                              void* d_out, int out_size) {
    const float* T_static = (const float*)d_in[0];
    const unsigned int* us = (const unsigned int*)d_in[1];
    const int* tum = (const int*)d_in[2];
    const float* e0 = (const float*)d_in[3];
    const float* e1 = (const float*)d_in[4];
    const float* e2 = (const float*)d_in[5];
    const float* e3 = (const float*)d_in[6];
    const float* e4 = (const float*)d_in[7];
    const float* e5 = (const float*)d_in[8];
    float* out = (float*)d_out;

    cudaFuncSetAttribute(accum_kernel, cudaFuncAttributeMaxDynamicSharedMemorySize,
                         SMEM_TOTAL);
    prep_kernel<<<KPAD / 64, 256>>>(us, e0, e1, e2, e3, e4, e5);
    accum_kernel<<<NMB * NSPLIT, NTHR, SMEM_TOTAL>>>(tum);
    finalize_kernel<<<(TN * OUTC + 255) / 256, 256>>>(T_static, out);
}